// round 6
// baseline (speedup 1.0000x reference)
#include <cuda_runtime.h>
#include <cstdint>

#define FULLMASK 0xffffffffu

// Scratch (device globals — no allocation allowed)
// g_stats[b] = {ssh, ssr, sum_top16(h), sum_top16(-h)}  (raw, un-normalized)
__device__ float g_stats[32][4];
__device__ float g_part[32 * 32 * 1024];   // [kg][b][c] split-K partials
__device__ int   g_done  = 0;              // producer completion counter
__device__ int   g_done2 = 0;              // reducer completion counter

// Monotone float -> uint key (ascending).
__device__ __forceinline__ unsigned key_encode(float f) {
    unsigned u = __float_as_uint(f);
    return (u & 0x80000000u) ? ~u : (u | 0x80000000u);
}
__device__ __forceinline__ float key_decode(unsigned k) {
    unsigned u = (k & 0x80000000u) ? (k & 0x7fffffffu) : ~k;
    return __uint_as_float(u);
}

// ---------------------------------------------------------------------------
// Kernel 1: per batch row b — row norms + exact top16(h) and top16(-h) sums.
// ONE 256-bin histogram over key>>24 serves both selections (neg bin = 255-bin).
// Then gather threshold-bin candidates to smem; warp 0 pops the remaining
// pos winners while warp 1 pops neg winners, concurrently. grid 32, block 256.
// ---------------------------------------------------------------------------
__global__ void __launch_bounds__(256) k1_stats(
        const float* __restrict__ f_rad, const float* __restrict__ f_histo) {
    const int b    = blockIdx.x;
    const int tid  = threadIdx.x;
    const int lane = tid & 31;
    const int wid  = tid >> 5;
    const float* __restrict__ hrow = f_histo + b * 2048;
    const float* __restrict__ rrow = f_rad   + b * 1024;

    __shared__ unsigned hist[8][256];
    __shared__ unsigned bufp[2048], bufn[2048];
    __shared__ unsigned s_cnt[2];     // gather counters
    __shared__ unsigned s_thr[2];     // threshold bins (pos, neg)
    __shared__ unsigned s_rem[2];     // remaining picks within threshold bin
    __shared__ unsigned s_wtot[8];
    __shared__ float    s_red[4][8];
    __shared__ float    s_sel[2];

    // --- load rows, encode keys, sums of squares ---
    float hv[8];
    float ssh = 0.f, ssr = 0.f;
    unsigned keys[8];
    #pragma unroll
    for (int u = 0; u < 8; ++u) {
        float v = hrow[u * 256 + tid];
        hv[u] = v;
        ssh += v * v;
        keys[u] = key_encode(v);
    }
    #pragma unroll
    for (int u = 0; u < 4; ++u) {
        float v = rrow[u * 256 + tid];
        ssr += v * v;
    }

    // --- warp-private histogram of key >> 24 ---
    #pragma unroll
    for (int j = 0; j < 8; ++j) hist[wid][lane + 32 * j] = 0u;
    if (tid < 2) s_cnt[tid] = 0u;
    __syncwarp();
    #pragma unroll
    for (int u = 0; u < 8; ++u)
        atomicAdd(&hist[wid][keys[u] >> 24], 1u);
    __syncthreads();

    // --- merge + dual-direction scan over 256 bins (bin = tid) ---
    unsigned c = 0u;
    #pragma unroll
    for (int w = 0; w < 8; ++w) c += hist[w][tid];
    unsigned inc = c;   // suffix-inclusive within warp (lanes >= lane)
    #pragma unroll
    for (int o = 1; o < 32; o <<= 1) {
        unsigned v = __shfl_down_sync(FULLMASK, inc, o);
        if (lane + o < 32) inc += v;
    }
    if (lane == 0) s_wtot[wid] = inc;
    __syncthreads();
    unsigned hi = 0u;
    #pragma unroll
    for (int w = 0; w < 8; ++w)
        if (w > wid) hi += s_wtot[w];
    unsigned cum   = (inc - c) + hi;        // # keys in bins strictly above tid
    unsigned below = 2048u - cum - c;       // # keys in bins strictly below tid
    if (cum < 16u && cum + c >= 16u)     { s_thr[0] = (unsigned)tid; s_rem[0] = 16u - cum; }
    if (below < 16u && below + c >= 16u) { s_thr[1] = (unsigned)tid; s_rem[1] = 16u - below; }
    __syncthreads();

    const unsigned tp = s_thr[0];
    const unsigned tn = s_thr[1];

    // --- sweep: sums outside threshold bins + gather candidates ---
    float sumA = 0.f, sumB = 0.f;
    #pragma unroll
    for (int u = 0; u < 8; ++u) {
        unsigned bin = keys[u] >> 24;
        if (bin > tp)       sumA += hv[u];
        else if (bin == tp) bufp[atomicAdd(&s_cnt[0], 1u)] = keys[u];
        if (bin < tn)       sumB += (-hv[u]);
        else if (bin == tn) bufn[atomicAdd(&s_cnt[1], 1u)] = ~keys[u];
    }

    // --- block reduce {ssh, ssr, sumA, sumB} ---
    #pragma unroll
    for (int o = 16; o; o >>= 1) {
        ssh  += __shfl_xor_sync(FULLMASK, ssh,  o);
        ssr  += __shfl_xor_sync(FULLMASK, ssr,  o);
        sumA += __shfl_xor_sync(FULLMASK, sumA, o);
        sumB += __shfl_xor_sync(FULLMASK, sumB, o);
    }
    if (lane == 0) {
        s_red[0][wid] = ssh;  s_red[1][wid] = ssr;
        s_red[2][wid] = sumA; s_red[3][wid] = sumB;
    }
    __syncthreads();

    // --- parallel tails: warp 0 pops pos, warp 1 pops neg ---
    if (wid < 2) {
        unsigned*      buf = wid ? bufn : bufp;
        const unsigned cnt = s_cnt[wid];
        const unsigned rem = s_rem[wid];
        float sum = 0.f;
        for (unsigned r = 0; r < rem; ++r) {
            unsigned m = 0u; int mi = -1;
            for (int j = lane; j < (int)cnt; j += 32) {
                unsigned v = buf[j];
                if (v > m) { m = v; mi = j; }
            }
            unsigned g    = __reduce_max_sync(FULLMASK, m);
            unsigned ball = __ballot_sync(FULLMASK, m == g);
            if (lane == __ffs(ball) - 1) buf[mi] = 0u;
            sum += wid ? -key_decode(~g) : key_decode(g);
            __syncwarp();
        }
        if (lane == 0) s_sel[wid] = sum;
    }
    __syncthreads();

    if (tid == 0) {
        float a0 = 0.f, a1 = 0.f, a2 = 0.f, a3 = 0.f;
        #pragma unroll
        for (int w = 0; w < 8; ++w) {
            a0 += s_red[0][w]; a1 += s_red[1][w];
            a2 += s_red[2][w]; a3 += s_red[3][w];
        }
        g_stats[b][0] = a0;              // ssh
        g_stats[b][1] = a1;              // ssr
        g_stats[b][2] = a2 + s_sel[0];   // sum top16(h)
        g_stats[b][3] = a3 + s_sel[1];   // sum top16(-h)
    }
}

// ---------------------------------------------------------------------------
// Kernel 2 (fused GEMM + reduce):
//   kg < 32  : producer — split-K fp32 GEMM partial with feat computed inline.
//              Block tile 32b x 64c x 64k, 32 threads, 8x8 interleaved tiles.
//   kg >= 32 : reducer — waits for all 512 producers (release/acquire gate),
//              then sums 32 partials + bias + token*flag and writes output.
// grid (16, 48), block 32.  All 768 CTAs are co-resident (one wave).
// ---------------------------------------------------------------------------
__global__ void __launch_bounds__(32) k2_fused(
        const float* __restrict__ W, const float* __restrict__ f_rad,
        const float* __restrict__ bias, const float* __restrict__ token,
        const unsigned char* __restrict__ rad_mask,
        const unsigned char* __restrict__ histo_mask,
        float* __restrict__ out) {
    __shared__ float Ws[64 * 68];
    __shared__ float Fs[32 * 68];
    __shared__ float sm_ca[32], sm_cb[32];
    const int tid = threadIdx.x;
    const int kg  = blockIdx.y;

    if (kg >= 32) {
        // ================= REDUCER =================
        const int rid = (kg - 32) * 16 + blockIdx.x;   // 0..255
        const int gid = rid * 32 + tid;                // float4 id 0..8191
        const int b   = gid >> 8;
        const int c4  = gid & 255;

        // acquire gate: all 512 producer partials visible
        while (*(volatile int*)&g_done != 512) { }
        __threadfence();

        float4 acc = *(const float4*)&bias[c4 * 4];
        #pragma unroll
        for (int g = 0; g < 32; ++g) {
            float4 p = *(const float4*)&g_part[g * 32768 + b * 1024 + c4 * 4];
            acc.x += p.x; acc.y += p.y; acc.z += p.z; acc.w += p.w;
        }
        float flag = (rad_mask[b] != 0 && histo_mask[b] != 0) ? 0.f : 1.f;
        float4 tk  = *(const float4*)&token[c4 * 4];
        acc.x += tk.x * flag; acc.y += tk.y * flag;
        acc.z += tk.z * flag; acc.w += tk.w * flag;
        *(float4*)&out[b * 1024 + c4 * 4] = acc;

        // last reducer resets both counters for the next graph replay
        if (tid == 0) {
            if (atomicAdd(&g_done2, 1) == 255) {
                atomicExch(&g_done, 0);
                atomicExch(&g_done2, 0);
            }
        }
        return;
    }

    // ================= PRODUCER =================
    const int c0  = blockIdx.x * 64;
    const int k0  = kg * 64;           // global feat column base
    const bool pos_half = (kg < 16);
    const int i0  = (kg & 15) * 64;    // f_rad column base for this k-slice

    // Per-row coefficients: feat = fr * (fr>=0 ? ca : cb)
    {
        float4 st = *(const float4*)&g_stats[tid][0];   // ssh, ssr, top, bng
        float nh = fmaxf(sqrtf(st.x), 1e-12f);
        float nr = fmaxf(sqrtf(st.y), 1e-12f);
        float inv_nr = 1.f / nr;
        float T  = st.z / (16.f * nh);    // mean(top16(h_norm))
        float Bt = -st.w / (16.f * nh);   // mean(bottom16(h_norm))
        if (pos_half) { sm_ca[tid] = inv_nr * T;   sm_cb[tid] = inv_nr * Bt; }
        else          { sm_ca[tid] = -inv_nr * Bt; sm_cb[tid] = -inv_nr * T; }
    }
    __syncwarp();

    // Load W tile 64c x 64k (1024 float4).
    #pragma unroll
    for (int it = 0; it < 32; ++it) {
        int idx = it * 32 + tid;
        int r   = idx >> 4;               // 0..63
        int q   = idx & 15;               // 0..15
        float4 v = *(const float4*)&W[(c0 + r) * 2048 + k0 + q * 4];
        *(float4*)&Ws[r * 68 + q * 4] = v;
    }
    // Build feat tile 32b x 64k inline from f_rad (512 float4).
    #pragma unroll
    for (int it = 0; it < 16; ++it) {
        int idx = it * 32 + tid;
        int r   = idx >> 4;               // 0..31
        int q   = idx & 15;
        float4 f = *(const float4*)&f_rad[r * 1024 + i0 + q * 4];
        float ca = sm_ca[r], cb = sm_cb[r];
        float4 v;
        v.x = f.x * (f.x >= 0.f ? ca : cb);
        v.y = f.y * (f.y >= 0.f ? ca : cb);
        v.z = f.z * (f.z >= 0.f ? ca : cb);
        v.w = f.w * (f.w >= 0.f ? ca : cb);
        *(float4*)&Fs[r * 68 + q * 4] = v;
    }
    __syncwarp();

    const int bl = tid >> 3;   // 0..3 : b rows  bl, bl+4, ..., bl+28
    const int cl = tid & 7;    // 0..7 : c cols  cl, cl+8, ..., cl+56

    float acc[8][8];
    #pragma unroll
    for (int i = 0; i < 8; ++i)
        #pragma unroll
        for (int j = 0; j < 8; ++j) acc[i][j] = 0.f;

    #pragma unroll
    for (int kq = 0; kq < 16; ++kq) {
        float4 f[8], w[8];
        #pragma unroll
        for (int i = 0; i < 8; ++i)
            f[i] = *(const float4*)&Fs[(bl + 4 * i) * 68 + kq * 4];
        #pragma unroll
        for (int j = 0; j < 8; ++j)
            w[j] = *(const float4*)&Ws[(cl + 8 * j) * 68 + kq * 4];
        #pragma unroll
        for (int i = 0; i < 8; ++i)
            #pragma unroll
            for (int j = 0; j < 8; ++j) {
                acc[i][j] = fmaf(f[i].x, w[j].x, acc[i][j]);
                acc[i][j] = fmaf(f[i].y, w[j].y, acc[i][j]);
                acc[i][j] = fmaf(f[i].z, w[j].z, acc[i][j]);
                acc[i][j] = fmaf(f[i].w, w[j].w, acc[i][j]);
            }
    }

    float* __restrict__ outp = g_part + kg * (32 * 1024) + c0;
    #pragma unroll
    for (int i = 0; i < 8; ++i) {
        #pragma unroll
        for (int j = 0; j < 8; ++j)
            outp[(bl + 4 * i) * 1024 + cl + 8 * j] = acc[i][j];
    }

    // release: partials visible, then count up
    __threadfence();
    if (tid == 0) atomicAdd(&g_done, 1);
}

// ---------------------------------------------------------------------------
extern "C" void kernel_launch(void* const* d_in, const int* in_sizes, int n_in,
                              void* d_out, int out_size) {
    const float*         f_rad      = (const float*)d_in[0];
    const float*         f_histo    = (const float*)d_in[1];
    const unsigned char* rad_mask   = (const unsigned char*)d_in[2];
    const unsigned char* histo_mask = (const unsigned char*)d_in[3];
    const float*         W          = (const float*)d_in[4];
    const float*         bias       = (const float*)d_in[5];
    const float*         token      = (const float*)d_in[6];
    float*               out        = (float*)d_out;

    k1_stats<<<32, 256>>>(f_rad, f_histo);
    k2_fused<<<dim3(16, 48), 32>>>(W, f_rad, bias, token,
                                   rad_mask, histo_mask, out);
}

// round 7
// speedup vs baseline: 1.0534x; 1.0534x over previous
#include <cuda_runtime.h>
#include <cstdint>

#define FULLMASK 0xffffffffu

// Scratch (device globals — no allocation allowed)
// g_stats[b] = {ssh, ssr, sum_top16(h), sum_top16(-h)}  (raw, un-normalized)
__device__ float g_stats[32][4];
__device__ float g_part[64 * 32 * 1024];   // [kg][b][c] split-K partials (8MB)

// Monotone float -> uint key (ascending).
__device__ __forceinline__ unsigned key_encode(float f) {
    unsigned u = __float_as_uint(f);
    return (u & 0x80000000u) ? ~u : (u | 0x80000000u);
}
__device__ __forceinline__ float key_decode(unsigned k) {
    unsigned u = (k & 0x80000000u) ? (k & 0x7fffffffu) : ~k;
    return __uint_as_float(u);
}

// ---------------------------------------------------------------------------
// Kernel 1: per batch row b — row norms + exact top16(h) and top16(-h) sums.
// ONE 256-bin histogram over key>>24 serves both selections (neg bin = 255-bin).
// Gather threshold-bin candidates to smem; warp 0 pops remaining pos winners
// while warp 1 pops neg winners, concurrently. grid 32, block 256.
// ---------------------------------------------------------------------------
__global__ void __launch_bounds__(256) k1_stats(
        const float* __restrict__ f_rad, const float* __restrict__ f_histo) {
    const int b    = blockIdx.x;
    const int tid  = threadIdx.x;
    const int lane = tid & 31;
    const int wid  = tid >> 5;
    const float* __restrict__ hrow = f_histo + b * 2048;
    const float* __restrict__ rrow = f_rad   + b * 1024;

    __shared__ unsigned hist[8][256];
    __shared__ unsigned bufp[2048], bufn[2048];
    __shared__ unsigned s_cnt[2];
    __shared__ unsigned s_thr[2];
    __shared__ unsigned s_rem[2];
    __shared__ unsigned s_wtot[8];
    __shared__ float    s_red[4][8];
    __shared__ float    s_sel[2];

    float hv[8];
    float ssh = 0.f, ssr = 0.f;
    unsigned keys[8];
    #pragma unroll
    for (int u = 0; u < 8; ++u) {
        float v = hrow[u * 256 + tid];
        hv[u] = v;
        ssh += v * v;
        keys[u] = key_encode(v);
    }
    #pragma unroll
    for (int u = 0; u < 4; ++u) {
        float v = rrow[u * 256 + tid];
        ssr += v * v;
    }

    #pragma unroll
    for (int j = 0; j < 8; ++j) hist[wid][lane + 32 * j] = 0u;
    if (tid < 2) s_cnt[tid] = 0u;
    __syncwarp();
    #pragma unroll
    for (int u = 0; u < 8; ++u)
        atomicAdd(&hist[wid][keys[u] >> 24], 1u);
    __syncthreads();

    unsigned c = 0u;
    #pragma unroll
    for (int w = 0; w < 8; ++w) c += hist[w][tid];
    unsigned inc = c;
    #pragma unroll
    for (int o = 1; o < 32; o <<= 1) {
        unsigned v = __shfl_down_sync(FULLMASK, inc, o);
        if (lane + o < 32) inc += v;
    }
    if (lane == 0) s_wtot[wid] = inc;
    __syncthreads();
    unsigned hi = 0u;
    #pragma unroll
    for (int w = 0; w < 8; ++w)
        if (w > wid) hi += s_wtot[w];
    unsigned cum   = (inc - c) + hi;
    unsigned below = 2048u - cum - c;
    if (cum < 16u && cum + c >= 16u)     { s_thr[0] = (unsigned)tid; s_rem[0] = 16u - cum; }
    if (below < 16u && below + c >= 16u) { s_thr[1] = (unsigned)tid; s_rem[1] = 16u - below; }
    __syncthreads();

    const unsigned tp = s_thr[0];
    const unsigned tn = s_thr[1];

    float sumA = 0.f, sumB = 0.f;
    #pragma unroll
    for (int u = 0; u < 8; ++u) {
        unsigned bin = keys[u] >> 24;
        if (bin > tp)       sumA += hv[u];
        else if (bin == tp) bufp[atomicAdd(&s_cnt[0], 1u)] = keys[u];
        if (bin < tn)       sumB += (-hv[u]);
        else if (bin == tn) bufn[atomicAdd(&s_cnt[1], 1u)] = ~keys[u];
    }

    #pragma unroll
    for (int o = 16; o; o >>= 1) {
        ssh  += __shfl_xor_sync(FULLMASK, ssh,  o);
        ssr  += __shfl_xor_sync(FULLMASK, ssr,  o);
        sumA += __shfl_xor_sync(FULLMASK, sumA, o);
        sumB += __shfl_xor_sync(FULLMASK, sumB, o);
    }
    if (lane == 0) {
        s_red[0][wid] = ssh;  s_red[1][wid] = ssr;
        s_red[2][wid] = sumA; s_red[3][wid] = sumB;
    }
    __syncthreads();

    if (wid < 2) {
        unsigned*      buf = wid ? bufn : bufp;
        const unsigned cnt = s_cnt[wid];
        const unsigned rem = s_rem[wid];
        float sum = 0.f;
        for (unsigned r = 0; r < rem; ++r) {
            unsigned m = 0u; int mi = -1;
            for (int j = lane; j < (int)cnt; j += 32) {
                unsigned v = buf[j];
                if (v > m) { m = v; mi = j; }
            }
            unsigned g    = __reduce_max_sync(FULLMASK, m);
            unsigned ball = __ballot_sync(FULLMASK, m == g);
            if (lane == __ffs(ball) - 1) buf[mi] = 0u;
            sum += wid ? -key_decode(~g) : key_decode(g);
            __syncwarp();
        }
        if (lane == 0) s_sel[wid] = sum;
    }
    __syncthreads();

    if (tid == 0) {
        float a0 = 0.f, a1 = 0.f, a2 = 0.f, a3 = 0.f;
        #pragma unroll
        for (int w = 0; w < 8; ++w) {
            a0 += s_red[0][w]; a1 += s_red[1][w];
            a2 += s_red[2][w]; a3 += s_red[3][w];
        }
        g_stats[b][0] = a0;
        g_stats[b][1] = a1;
        g_stats[b][2] = a2 + s_sel[0];
        g_stats[b][3] = a3 + s_sel[1];
    }
}

// ---------------------------------------------------------------------------
// Kernel 2: split-K fp32 GEMM, feat computed inline from f_rad + stats.
// 128 threads = 4 warps (one per SMSP!). CTA tile 32b x 64c x 128k; each warp
// owns split-K slice kg = blockIdx.y*4 + wid (32 k's), thread tile 8b x 8c
// interleaved. Smem stride 132 -> conflict-free float4 access.
// grid (16 cblk, 16 kq) = 256 CTAs = 1024 warps (~1.7 per SMSP).
// blockIdx.y < 8 -> pos half of feat; >= 8 -> neg half.
// ---------------------------------------------------------------------------
__global__ void __launch_bounds__(128) k2_gemm(const float* __restrict__ W,
                                               const float* __restrict__ f_rad) {
    __shared__ float Ws[64 * 132];
    __shared__ float Fs[32 * 132];
    __shared__ float sm_ca[32], sm_cb[32];
    const int tid = threadIdx.x;
    const int lane = tid & 31;
    const int wid  = tid >> 5;           // 0..3 -> SMSP, split-K sub-slice
    const int c0  = blockIdx.x * 64;
    const int by  = blockIdx.y;          // 0..15
    const int k0  = by * 128;            // global feat column base (CTA)
    const bool pos_half = (by < 8);
    const int i0  = (by & 7) * 128;      // f_rad column base (CTA)

    // Per-row coefficients: feat = fr * (fr>=0 ? ca : cb)
    if (tid < 32) {
        float4 st = *(const float4*)&g_stats[tid][0];   // ssh, ssr, top, bng
        float nh = fmaxf(sqrtf(st.x), 1e-12f);
        float nr = fmaxf(sqrtf(st.y), 1e-12f);
        float inv_nr = 1.f / nr;
        float T  = st.z / (16.f * nh);
        float Bt = -st.w / (16.f * nh);
        if (pos_half) { sm_ca[tid] = inv_nr * T;   sm_cb[tid] = inv_nr * Bt; }
        else          { sm_ca[tid] = -inv_nr * Bt; sm_cb[tid] = -inv_nr * T; }
    }
    __syncthreads();

    // Load W tile 64c x 128k (2048 float4, coalesced).
    #pragma unroll
    for (int it = 0; it < 16; ++it) {
        int idx = it * 128 + tid;
        int r   = idx >> 5;               // 0..63
        int q   = idx & 31;               // 0..31
        float4 v = *(const float4*)&W[(c0 + r) * 2048 + k0 + q * 4];
        *(float4*)&Ws[r * 132 + q * 4] = v;
    }
    // Build feat tile 32b x 128k inline from f_rad (1024 float4).
    #pragma unroll
    for (int it = 0; it < 8; ++it) {
        int idx = it * 128 + tid;
        int r   = idx >> 5;               // 0..31
        int q   = idx & 31;
        float4 f = *(const float4*)&f_rad[r * 1024 + i0 + q * 4];
        float ca = sm_ca[r], cb = sm_cb[r];
        float4 v;
        v.x = f.x * (f.x >= 0.f ? ca : cb);
        v.y = f.y * (f.y >= 0.f ? ca : cb);
        v.z = f.z * (f.z >= 0.f ? ca : cb);
        v.w = f.w * (f.w >= 0.f ? ca : cb);
        *(float4*)&Fs[r * 132 + q * 4] = v;
    }
    __syncthreads();

    const int bl = lane >> 3;   // 0..3 : b rows  bl, bl+4, ..., bl+28
    const int cl = lane & 7;    // 0..7 : c cols  cl, cl+8, ..., cl+56
    const int qb = wid * 8;     // this warp's k-slice: float4 ids qb..qb+7

    float acc[8][8];
    #pragma unroll
    for (int i = 0; i < 8; ++i)
        #pragma unroll
        for (int j = 0; j < 8; ++j) acc[i][j] = 0.f;

    #pragma unroll
    for (int kq = 0; kq < 8; ++kq) {
        float4 f[8], w[8];
        #pragma unroll
        for (int i = 0; i < 8; ++i)
            f[i] = *(const float4*)&Fs[(bl + 4 * i) * 132 + (qb + kq) * 4];
        #pragma unroll
        for (int j = 0; j < 8; ++j)
            w[j] = *(const float4*)&Ws[(cl + 8 * j) * 132 + (qb + kq) * 4];
        #pragma unroll
        for (int i = 0; i < 8; ++i)
            #pragma unroll
            for (int j = 0; j < 8; ++j) {
                acc[i][j] = fmaf(f[i].x, w[j].x, acc[i][j]);
                acc[i][j] = fmaf(f[i].y, w[j].y, acc[i][j]);
                acc[i][j] = fmaf(f[i].z, w[j].z, acc[i][j]);
                acc[i][j] = fmaf(f[i].w, w[j].w, acc[i][j]);
            }
    }

    const int kg = by * 4 + wid;          // 0..63
    float* __restrict__ outp = g_part + kg * (32 * 1024) + c0;
    #pragma unroll
    for (int i = 0; i < 8; ++i) {
        #pragma unroll
        for (int j = 0; j < 8; ++j)
            outp[(bl + 4 * i) * 1024 + cl + 8 * j] = acc[i][j];
    }
}

// ---------------------------------------------------------------------------
// Kernel 3: reduce 64 split-K partials + bias + token * flag. grid 64, blk 128.
// ---------------------------------------------------------------------------
__global__ void __launch_bounds__(128) k3_reduce(
        const float* __restrict__ bias, const float* __restrict__ token,
        const unsigned char* __restrict__ rad_mask,
        const unsigned char* __restrict__ histo_mask,
        float* __restrict__ out) {
    int gid = blockIdx.x * 128 + threadIdx.x;   // float4 id 0..8191
    int b   = gid >> 8;
    int c4  = gid & 255;

    float4 acc = *(const float4*)&bias[c4 * 4];
    #pragma unroll
    for (int g = 0; g < 64; ++g) {
        float4 p = *(const float4*)&g_part[g * 32768 + b * 1024 + c4 * 4];
        acc.x += p.x; acc.y += p.y; acc.z += p.z; acc.w += p.w;
    }
    float flag = (rad_mask[b] != 0 && histo_mask[b] != 0) ? 0.f : 1.f;
    float4 tk  = *(const float4*)&token[c4 * 4];
    acc.x += tk.x * flag; acc.y += tk.y * flag;
    acc.z += tk.z * flag; acc.w += tk.w * flag;
    *(float4*)&out[b * 1024 + c4 * 4] = acc;
}

// ---------------------------------------------------------------------------
extern "C" void kernel_launch(void* const* d_in, const int* in_sizes, int n_in,
                              void* d_out, int out_size) {
    const float*         f_rad      = (const float*)d_in[0];
    const float*         f_histo    = (const float*)d_in[1];
    const unsigned char* rad_mask   = (const unsigned char*)d_in[2];
    const unsigned char* histo_mask = (const unsigned char*)d_in[3];
    const float*         W          = (const float*)d_in[4];
    const float*         bias       = (const float*)d_in[5];
    const float*         token      = (const float*)d_in[6];
    float*               out        = (float*)d_out;

    k1_stats<<<32, 256>>>(f_rad, f_histo);
    k2_gemm<<<dim3(16, 16), 128>>>(W, f_rad);
    k3_reduce<<<64, 128>>>(bias, token, rad_mask, histo_mask, out);
}

// round 8
// speedup vs baseline: 1.1312x; 1.0739x over previous
#include <cuda_runtime.h>
#include <cstdint>

#define FULLMASK 0xffffffffu

// Scratch (device globals — no allocation allowed)
// g_stats[b] = {ssh, ssr, sum_top16(h), sum_top16(-h)}  (raw, un-normalized)
__device__ float g_stats[32][4];

// Monotone float -> uint key (ascending). key(-f) == ~key(f).
__device__ __forceinline__ unsigned key_encode(float f) {
    unsigned u = __float_as_uint(f);
    return (u & 0x80000000u) ? ~u : (u | 0x80000000u);
}
__device__ __forceinline__ float key_decode(unsigned k) {
    unsigned u = (k & 0x80000000u) ? (k & 0x7fffffffu) : ~k;
    return __uint_as_float(u);
}

// ---------------------------------------------------------------------------
// Kernel 1: grid 64 = (row b, sign s), block 256. Each block does ONE exact
// top-16 selection (s=0: top16(h), s=1: top16(-h)) via one 256-bin exponent
// histogram + gathered REDUX tail, plus one sum-of-squares (s=0: ||h||^2,
// s=1: ||r||^2). s=1 blocks also pre-initialize out[b] = bias + token*flag
// (k2 atomic-accumulates on top; rewritten every graph replay).
// ---------------------------------------------------------------------------
__global__ void __launch_bounds__(256) k1_stats(
        const float* __restrict__ f_rad, const float* __restrict__ f_histo,
        const float* __restrict__ bias, const float* __restrict__ token,
        const unsigned char* __restrict__ rad_mask,
        const unsigned char* __restrict__ histo_mask,
        float* __restrict__ out) {
    const int b    = blockIdx.x >> 1;
    const int s    = blockIdx.x & 1;
    const int tid  = threadIdx.x;
    const int lane = tid & 31;
    const int wid  = tid >> 5;
    const float* __restrict__ hrow = f_histo + b * 2048;
    const float* __restrict__ rrow = f_rad   + b * 1024;

    __shared__ unsigned hist[8][256];
    __shared__ unsigned buf[2048];
    __shared__ unsigned s_cnt;
    __shared__ unsigned s_thr, s_rem;
    __shared__ unsigned s_wtot[8];
    __shared__ float    s_red[2][8];
    __shared__ float    s_sel;

    // --- load rows, encode (sign-flipped for s=1) keys, sum of squares ---
    float hv[8];
    float ssq = 0.f;
    unsigned keys[8];
    #pragma unroll
    for (int u = 0; u < 8; ++u) {
        float v = hrow[u * 256 + tid];
        hv[u] = v;
        if (s == 0) ssq += v * v;
        unsigned e = key_encode(v);
        keys[u] = s ? ~e : e;
    }
    if (s == 1) {
        #pragma unroll
        for (int u = 0; u < 4; ++u) {
            float v = rrow[u * 256 + tid];
            ssq += v * v;
        }
        // out init: bias + token * flag (one float4 per thread)
        float flag = (rad_mask[b] != 0 && histo_mask[b] != 0) ? 0.f : 1.f;
        float4 bv = *(const float4*)&bias[tid * 4];
        float4 tv = *(const float4*)&token[tid * 4];
        bv.x += tv.x * flag; bv.y += tv.y * flag;
        bv.z += tv.z * flag; bv.w += tv.w * flag;
        *(float4*)&out[b * 1024 + tid * 4] = bv;
    }

    // --- warp-private histogram of key >> 24 ---
    #pragma unroll
    for (int j = 0; j < 8; ++j) hist[wid][lane + 32 * j] = 0u;
    if (tid == 0) s_cnt = 0u;
    __syncwarp();
    #pragma unroll
    for (int u = 0; u < 8; ++u)
        atomicAdd(&hist[wid][keys[u] >> 24], 1u);
    __syncthreads();

    // --- merge + suffix scan over 256 bins (bin = tid) ---
    unsigned c = 0u;
    #pragma unroll
    for (int w = 0; w < 8; ++w) c += hist[w][tid];
    unsigned inc = c;
    #pragma unroll
    for (int o = 1; o < 32; o <<= 1) {
        unsigned v = __shfl_down_sync(FULLMASK, inc, o);
        if (lane + o < 32) inc += v;
    }
    if (lane == 0) s_wtot[wid] = inc;
    __syncthreads();
    unsigned hi = 0u;
    #pragma unroll
    for (int w = 0; w < 8; ++w)
        if (w > wid) hi += s_wtot[w];
    unsigned cum = (inc - c) + hi;          // # keys in bins strictly above tid
    if (cum < 16u && cum + c >= 16u) { s_thr = (unsigned)tid; s_rem = 16u - cum; }
    __syncthreads();

    const unsigned tp  = s_thr;
    const unsigned rem = s_rem;

    // --- sweep: sum above threshold bin; gather candidates in it ---
    float sum = 0.f;
    #pragma unroll
    for (int u = 0; u < 8; ++u) {
        unsigned bin = keys[u] >> 24;
        float val = s ? -hv[u] : hv[u];
        if (bin > tp)       sum += val;
        else if (bin == tp) buf[atomicAdd(&s_cnt, 1u)] = keys[u];
    }

    // --- block reduce {ssq, sum} ---
    #pragma unroll
    for (int o = 16; o; o >>= 1) {
        ssq += __shfl_xor_sync(FULLMASK, ssq, o);
        sum += __shfl_xor_sync(FULLMASK, sum, o);
    }
    if (lane == 0) { s_red[0][wid] = ssq; s_red[1][wid] = sum; }
    __syncthreads();

    // --- tail: warp 0 pops the remaining `rem` winners from the candidates ---
    if (wid == 0) {
        const unsigned cnt = s_cnt;
        float tsum = 0.f;
        for (unsigned r = 0; r < rem; ++r) {
            unsigned m = 0u; int mi = -1;
            for (int j = lane; j < (int)cnt; j += 32) {
                unsigned v = buf[j];
                if (v > m) { m = v; mi = j; }
            }
            unsigned g    = __reduce_max_sync(FULLMASK, m);
            unsigned ball = __ballot_sync(FULLMASK, m == g);
            if (lane == __ffs(ball) - 1) buf[mi] = 0u;
            tsum += s ? -key_decode(~g) : key_decode(g);
            __syncwarp();
        }
        if (lane == 0) s_sel = tsum;
    }
    __syncthreads();

    if (tid == 0) {
        float a0 = 0.f, a1 = 0.f;
        #pragma unroll
        for (int w = 0; w < 8; ++w) { a0 += s_red[0][w]; a1 += s_red[1][w]; }
        if (s == 0) { g_stats[b][0] = a0; g_stats[b][2] = a1 + s_sel; }
        else        { g_stats[b][1] = a0; g_stats[b][3] = a1 + s_sel; }
    }
}

// ---------------------------------------------------------------------------
// Kernel 2: split-K fp32 GEMM, feat built inline from f_rad + stats; 4-warp
// split-K slices reduced in smem, result atomically accumulated into out
// (pre-initialized with bias + token*flag by k1). No partial buffers, no k3.
// 128 threads (1 warp/SMSP), CTA tile 32b x 64c x 128k; warp w: 32 k's.
// grid (16 cblk, 16 kq): by<8 -> pos half of feat, by>=8 -> neg half.
// ---------------------------------------------------------------------------
__global__ void __launch_bounds__(128) k2_gemm(const float* __restrict__ W,
                                               const float* __restrict__ f_rad,
                                               float* __restrict__ out) {
    __shared__ float Ws[64 * 132];     // W tile; reused as reduction buffer
    __shared__ float Fs[32 * 132];
    __shared__ float sm_ca[32], sm_cb[32];
    const int tid = threadIdx.x;
    const int lane = tid & 31;
    const int wid  = tid >> 5;           // 0..3 -> SMSP + split-K sub-slice
    const int c0  = blockIdx.x * 64;
    const int by  = blockIdx.y;          // 0..15
    const int k0  = by * 128;            // global feat column base (CTA)
    const bool pos_half = (by < 8);
    const int i0  = (by & 7) * 128;      // f_rad column base (CTA)

    // Per-row coefficients: feat = fr * (fr>=0 ? ca : cb)
    if (tid < 32) {
        float4 st = *(const float4*)&g_stats[tid][0];   // ssh, ssr, top, bng
        float nh = fmaxf(sqrtf(st.x), 1e-12f);
        float nr = fmaxf(sqrtf(st.y), 1e-12f);
        float inv_nr = 1.f / nr;
        float T  = st.z / (16.f * nh);
        float Bt = -st.w / (16.f * nh);
        if (pos_half) { sm_ca[tid] = inv_nr * T;   sm_cb[tid] = inv_nr * Bt; }
        else          { sm_ca[tid] = -inv_nr * Bt; sm_cb[tid] = -inv_nr * T; }
    }
    __syncthreads();

    // Load W tile 64c x 128k (2048 float4, coalesced).
    #pragma unroll
    for (int it = 0; it < 16; ++it) {
        int idx = it * 128 + tid;
        int r   = idx >> 5;               // 0..63
        int q   = idx & 31;               // 0..31
        float4 v = *(const float4*)&W[(c0 + r) * 2048 + k0 + q * 4];
        *(float4*)&Ws[r * 132 + q * 4] = v;
    }
    // Build feat tile 32b x 128k inline from f_rad (1024 float4).
    #pragma unroll
    for (int it = 0; it < 8; ++it) {
        int idx = it * 128 + tid;
        int r   = idx >> 5;               // 0..31
        int q   = idx & 31;
        float4 f = *(const float4*)&f_rad[r * 1024 + i0 + q * 4];
        float ca = sm_ca[r], cb = sm_cb[r];
        float4 v;
        v.x = f.x * (f.x >= 0.f ? ca : cb);
        v.y = f.y * (f.y >= 0.f ? ca : cb);
        v.z = f.z * (f.z >= 0.f ? ca : cb);
        v.w = f.w * (f.w >= 0.f ? ca : cb);
        *(float4*)&Fs[r * 132 + q * 4] = v;
    }
    __syncthreads();

    const int bl = lane >> 3;   // 0..3 : b rows  bl, bl+4, ..., bl+28
    const int cl = lane & 7;    // 0..7 : c cols  cl, cl+8, ..., cl+56
    const int qb = wid * 8;     // this warp's k-slice: float4 ids qb..qb+7

    float acc[8][8];
    #pragma unroll
    for (int i = 0; i < 8; ++i)
        #pragma unroll
        for (int j = 0; j < 8; ++j) acc[i][j] = 0.f;

    #pragma unroll
    for (int kq = 0; kq < 8; ++kq) {
        float4 f[8], w[8];
        #pragma unroll
        for (int i = 0; i < 8; ++i)
            f[i] = *(const float4*)&Fs[(bl + 4 * i) * 132 + (qb + kq) * 4];
        #pragma unroll
        for (int j = 0; j < 8; ++j)
            w[j] = *(const float4*)&Ws[(cl + 8 * j) * 132 + (qb + kq) * 4];
        #pragma unroll
        for (int i = 0; i < 8; ++i)
            #pragma unroll
            for (int j = 0; j < 8; ++j) {
                acc[i][j] = fmaf(f[i].x, w[j].x, acc[i][j]);
                acc[i][j] = fmaf(f[i].y, w[j].y, acc[i][j]);
                acc[i][j] = fmaf(f[i].z, w[j].z, acc[i][j]);
                acc[i][j] = fmaf(f[i].w, w[j].w, acc[i][j]);
            }
    }

    // --- intra-CTA reduction of the 4 warps' split-K tiles ---
    __syncthreads();                      // all warps done reading Ws
    float* red = Ws;                      // 4 x 2048 floats (fits in 8448)
    #pragma unroll
    for (int i = 0; i < 8; ++i)
        #pragma unroll
        for (int j = 0; j < 8; ++j)
            red[wid * 2048 + (bl + 4 * i) * 64 + (cl + 8 * j)] = acc[i][j];
    __syncthreads();

    // Each thread reduces 16 positions across the 4 warps, then REDG into out.
    #pragma unroll
    for (int p4 = 0; p4 < 4; ++p4) {
        int pos = tid * 16 + p4 * 4;      // 0..2047, float4-aligned
        float4 v = *(const float4*)&red[pos];
        #pragma unroll
        for (int w = 1; w < 4; ++w) {
            float4 t = *(const float4*)&red[w * 2048 + pos];
            v.x += t.x; v.y += t.y; v.z += t.z; v.w += t.w;
        }
        int brow = pos >> 6;              // 0..31
        int ccol = c0 + (pos & 63);
        float* o = &out[brow * 1024 + ccol];
        atomicAdd(o + 0, v.x);
        atomicAdd(o + 1, v.y);
        atomicAdd(o + 2, v.z);
        atomicAdd(o + 3, v.w);
    }
}

// ---------------------------------------------------------------------------
extern "C" void kernel_launch(void* const* d_in, const int* in_sizes, int n_in,
                              void* d_out, int out_size) {
    const float*         f_rad      = (const float*)d_in[0];
    const float*         f_histo    = (const float*)d_in[1];
    const unsigned char* rad_mask   = (const unsigned char*)d_in[2];
    const unsigned char* histo_mask = (const unsigned char*)d_in[3];
    const float*         W          = (const float*)d_in[4];
    const float*         bias       = (const float*)d_in[5];
    const float*         token      = (const float*)d_in[6];
    float*               out        = (float*)d_out;

    k1_stats<<<64, 256>>>(f_rad, f_histo, bias, token,
                          rad_mask, histo_mask, out);
    k2_gemm<<<dim3(16, 16), 128>>>(W, f_rad, out);
}

// round 9
// speedup vs baseline: 1.3993x; 1.2369x over previous
#include <cuda_runtime.h>
#include <cstdint>

#define FULLMASK 0xffffffffu

// Scratch (device globals — no allocation allowed)
// g_stats[b] = {ssh, ssr, sum_top16(h), sum_top16(-h)}  (raw, un-normalized)
__device__ float g_stats[32][4];

// Monotone float -> uint key (ascending). key(-f) == ~key(f).
__device__ __forceinline__ unsigned key_encode(float f) {
    unsigned u = __float_as_uint(f);
    return (u & 0x80000000u) ? ~u : (u | 0x80000000u);
}
__device__ __forceinline__ float key_decode(unsigned k) {
    unsigned u = (k & 0x80000000u) ? (k & 0x7fffffffu) : ~k;
    return __uint_as_float(u);
}

// ---------------------------------------------------------------------------
// Kernel 1: grid 64 = (row b, sign s), block 256. Each block does ONE exact
// top-16 selection (s=0: top16(h), s=1: top16(-h)) via one 256-bin exponent
// histogram + PARALLEL rank-select tail, plus one sum-of-squares.
// s=1 blocks also pre-initialize out[b] = bias + token*flag.
// ---------------------------------------------------------------------------
__global__ void __launch_bounds__(256) k1_stats(
        const float* __restrict__ f_rad, const float* __restrict__ f_histo,
        const float* __restrict__ bias, const float* __restrict__ token,
        const unsigned char* __restrict__ rad_mask,
        const unsigned char* __restrict__ histo_mask,
        float* __restrict__ out) {
    const int b    = blockIdx.x >> 1;
    const int s    = blockIdx.x & 1;
    const int tid  = threadIdx.x;
    const int lane = tid & 31;
    const int wid  = tid >> 5;
    const float* __restrict__ hrow = f_histo + b * 2048;
    const float* __restrict__ rrow = f_rad   + b * 1024;

    __shared__ unsigned hist[8][256];
    __shared__ unsigned buf[2048];
    __shared__ unsigned s_cnt;
    __shared__ unsigned s_thr, s_rem;
    __shared__ unsigned s_wtot[8];
    __shared__ float    s_red[2][8];

    // --- load rows, encode (sign-flipped for s=1) keys, sum of squares ---
    float hv[8];
    float ssq = 0.f;
    unsigned keys[8];
    #pragma unroll
    for (int u = 0; u < 8; ++u) {
        float v = hrow[u * 256 + tid];
        hv[u] = v;
        if (s == 0) ssq += v * v;
        unsigned e = key_encode(v);
        keys[u] = s ? ~e : e;
    }
    if (s == 1) {
        #pragma unroll
        for (int u = 0; u < 4; ++u) {
            float v = rrow[u * 256 + tid];
            ssq += v * v;
        }
        // out init: bias + token * flag (one float4 per thread)
        float flag = (rad_mask[b] != 0 && histo_mask[b] != 0) ? 0.f : 1.f;
        float4 bv = *(const float4*)&bias[tid * 4];
        float4 tv = *(const float4*)&token[tid * 4];
        bv.x += tv.x * flag; bv.y += tv.y * flag;
        bv.z += tv.z * flag; bv.w += tv.w * flag;
        *(float4*)&out[b * 1024 + tid * 4] = bv;
    }

    // --- warp-private histogram of key >> 24 ---
    #pragma unroll
    for (int j = 0; j < 8; ++j) hist[wid][lane + 32 * j] = 0u;
    if (tid == 0) s_cnt = 0u;
    __syncwarp();
    #pragma unroll
    for (int u = 0; u < 8; ++u)
        atomicAdd(&hist[wid][keys[u] >> 24], 1u);
    __syncthreads();

    // --- merge + suffix scan over 256 bins (bin = tid) ---
    unsigned c = 0u;
    #pragma unroll
    for (int w = 0; w < 8; ++w) c += hist[w][tid];
    unsigned inc = c;
    #pragma unroll
    for (int o = 1; o < 32; o <<= 1) {
        unsigned v = __shfl_down_sync(FULLMASK, inc, o);
        if (lane + o < 32) inc += v;
    }
    if (lane == 0) s_wtot[wid] = inc;
    __syncthreads();
    unsigned hi = 0u;
    #pragma unroll
    for (int w = 0; w < 8; ++w)
        if (w > wid) hi += s_wtot[w];
    unsigned cum = (inc - c) + hi;          // # keys in bins strictly above tid
    if (cum < 16u && cum + c >= 16u) { s_thr = (unsigned)tid; s_rem = 16u - cum; }
    __syncthreads();

    const unsigned tp  = s_thr;
    const unsigned rem = s_rem;

    // --- sweep: sum above threshold bin; gather candidates in it ---
    float sum = 0.f;
    #pragma unroll
    for (int u = 0; u < 8; ++u) {
        unsigned bin = keys[u] >> 24;
        float val = s ? -hv[u] : hv[u];
        if (bin > tp)       sum += val;
        else if (bin == tp) buf[atomicAdd(&s_cnt, 1u)] = keys[u];
    }
    __syncthreads();

    // --- parallel rank-select over the candidates (exact, index tie-break) ---
    const int cnt = (int)s_cnt;
    for (int i = tid; i < cnt; i += 256) {
        unsigned ki = buf[i];
        int rank = 0;
        for (int j = 0; j < cnt; ++j) {
            unsigned kj = buf[j];
            rank += (kj > ki) || (kj == ki && j < i);
        }
        if (rank < (int)rem)
            sum += s ? -key_decode(~ki) : key_decode(ki);
    }

    // --- block reduce {ssq, sum} ---
    #pragma unroll
    for (int o = 16; o; o >>= 1) {
        ssq += __shfl_xor_sync(FULLMASK, ssq, o);
        sum += __shfl_xor_sync(FULLMASK, sum, o);
    }
    if (lane == 0) { s_red[0][wid] = ssq; s_red[1][wid] = sum; }
    __syncthreads();

    if (tid == 0) {
        float a0 = 0.f, a1 = 0.f;
        #pragma unroll
        for (int w = 0; w < 8; ++w) { a0 += s_red[0][w]; a1 += s_red[1][w]; }
        if (s == 0) { g_stats[b][0] = a0; g_stats[b][2] = a1; }
        else        { g_stats[b][1] = a0; g_stats[b][3] = a1; }
    }
}

// ---------------------------------------------------------------------------
// Kernel 2: split-K fp32 GEMM, feat built inline from f_rad + stats.
// 512 CTAs x 128 threads (single co-resident wave, ~3.5 warps/SMSP).
// CTA tile 32b x 32c x 128k; warp w owns k-quarter (32 k's); thread tile
// 8b x 4c interleaved (b = bl+4i, c = cl+8j). Smem stride 132: conflict-free
// float4 loads. 4-warp split-K slices reduced in smem, then atomicAdd into
// out (pre-initialized with bias + token*flag by k1).
// grid (32 cblk, 16 ky): ky<8 -> pos half of feat, ky>=8 -> neg half.
// ---------------------------------------------------------------------------
__global__ void __launch_bounds__(128) k2_gemm(const float* __restrict__ W,
                                               const float* __restrict__ f_rad,
                                               float* __restrict__ out) {
    __shared__ float Ws[32 * 132];     // W tile; reused as reduction buffer
    __shared__ float Fs[32 * 132];
    __shared__ float sm_ca[32], sm_cb[32];
    const int tid = threadIdx.x;
    const int lane = tid & 31;
    const int wid  = tid >> 5;           // 0..3 -> SMSP + split-K sub-slice
    const int c0  = blockIdx.x * 32;
    const int by  = blockIdx.y;          // 0..15
    const int k0  = by * 128;            // global feat column base (CTA)
    const bool pos_half = (by < 8);
    const int i0  = (by & 7) * 128;      // f_rad column base (CTA)

    // Per-row coefficients: feat = fr * (fr>=0 ? ca : cb)
    if (tid < 32) {
        float4 st = *(const float4*)&g_stats[tid][0];   // ssh, ssr, top, bng
        float nh = fmaxf(sqrtf(st.x), 1e-12f);
        float nr = fmaxf(sqrtf(st.y), 1e-12f);
        float inv_nr = 1.f / nr;
        float T  = st.z / (16.f * nh);
        float Bt = -st.w / (16.f * nh);
        if (pos_half) { sm_ca[tid] = inv_nr * T;   sm_cb[tid] = inv_nr * Bt; }
        else          { sm_ca[tid] = -inv_nr * Bt; sm_cb[tid] = -inv_nr * T; }
    }
    __syncthreads();

    // Load W tile 32c x 128k (1024 float4, coalesced).
    #pragma unroll
    for (int it = 0; it < 8; ++it) {
        int idx = it * 128 + tid;
        int r   = idx >> 5;               // 0..31
        int q   = idx & 31;               // 0..31
        float4 v = *(const float4*)&W[(c0 + r) * 2048 + k0 + q * 4];
        *(float4*)&Ws[r * 132 + q * 4] = v;
    }
    // Build feat tile 32b x 128k inline from f_rad (1024 float4).
    #pragma unroll
    for (int it = 0; it < 8; ++it) {
        int idx = it * 128 + tid;
        int r   = idx >> 5;               // 0..31
        int q   = idx & 31;
        float4 f = *(const float4*)&f_rad[r * 1024 + i0 + q * 4];
        float ca = sm_ca[r], cb = sm_cb[r];
        float4 v;
        v.x = f.x * (f.x >= 0.f ? ca : cb);
        v.y = f.y * (f.y >= 0.f ? ca : cb);
        v.z = f.z * (f.z >= 0.f ? ca : cb);
        v.w = f.w * (f.w >= 0.f ? ca : cb);
        *(float4*)&Fs[r * 132 + q * 4] = v;
    }
    __syncthreads();

    const int bl = lane >> 3;   // 0..3 : b rows  bl, bl+4, ..., bl+28
    const int cl = lane & 7;    // 0..7 : c cols  cl, cl+8, cl+16, cl+24
    const int qb = wid * 8;     // this warp's k-slice: float4 ids qb..qb+7

    float acc[8][4];
    #pragma unroll
    for (int i = 0; i < 8; ++i)
        #pragma unroll
        for (int j = 0; j < 4; ++j) acc[i][j] = 0.f;

    #pragma unroll
    for (int kq = 0; kq < 8; ++kq) {
        float4 f[8], w[4];
        #pragma unroll
        for (int i = 0; i < 8; ++i)
            f[i] = *(const float4*)&Fs[(bl + 4 * i) * 132 + (qb + kq) * 4];
        #pragma unroll
        for (int j = 0; j < 4; ++j)
            w[j] = *(const float4*)&Ws[(cl + 8 * j) * 132 + (qb + kq) * 4];
        #pragma unroll
        for (int i = 0; i < 8; ++i)
            #pragma unroll
            for (int j = 0; j < 4; ++j) {
                acc[i][j] = fmaf(f[i].x, w[j].x, acc[i][j]);
                acc[i][j] = fmaf(f[i].y, w[j].y, acc[i][j]);
                acc[i][j] = fmaf(f[i].z, w[j].z, acc[i][j]);
                acc[i][j] = fmaf(f[i].w, w[j].w, acc[i][j]);
            }
    }

    // --- intra-CTA reduction of the 4 warps' split-K tiles ---
    __syncthreads();                      // all warps done reading Ws
    float* red = Ws;                      // 4 x 1024 floats (fits in 4224)
    #pragma unroll
    for (int i = 0; i < 8; ++i)
        #pragma unroll
        for (int j = 0; j < 4; ++j)
            red[wid * 1024 + (bl + 4 * i) * 32 + (cl + 8 * j)] = acc[i][j];
    __syncthreads();

    // Each thread reduces 8 positions across the 4 warps, then REDG into out.
    #pragma unroll
    for (int p = 0; p < 2; ++p) {
        int pos = tid * 8 + p * 4;        // 0..1023, float4-aligned
        float4 v = *(const float4*)&red[pos];
        #pragma unroll
        for (int w = 1; w < 4; ++w) {
            float4 t = *(const float4*)&red[w * 1024 + pos];
            v.x += t.x; v.y += t.y; v.z += t.z; v.w += t.w;
        }
        int brow = pos >> 5;              // 0..31
        int ccol = c0 + (pos & 31);
        float* o = &out[brow * 1024 + ccol];
        atomicAdd(o + 0, v.x);
        atomicAdd(o + 1, v.y);
        atomicAdd(o + 2, v.z);
        atomicAdd(o + 3, v.w);
    }
}

// ---------------------------------------------------------------------------
extern "C" void kernel_launch(void* const* d_in, const int* in_sizes, int n_in,
                              void* d_out, int out_size) {
    const float*         f_rad      = (const float*)d_in[0];
    const float*         f_histo    = (const float*)d_in[1];
    const unsigned char* rad_mask   = (const unsigned char*)d_in[2];
    const unsigned char* histo_mask = (const unsigned char*)d_in[3];
    const float*         W          = (const float*)d_in[4];
    const float*         bias       = (const float*)d_in[5];
    const float*         token      = (const float*)d_in[6];
    float*               out        = (float*)d_out;

    k1_stats<<<64, 256>>>(f_rad, f_histo, bias, token,
                          rad_mask, histo_mask, out);
    k2_gemm<<<dim3(32, 16), 128>>>(W, f_rad, out);
}